// round 1
// baseline (speedup 1.0000x reference)
#include <cuda_runtime.h>

#define HDIM 64
#define WSTRIDE 68          // 64 + 4 pad: conflict-free rows (LDS.128) AND columns (scalar)
#define NUM_GRAD_STEPS 4
#define INNER_LR 0.01f

// One block (64 threads) per batch element. Thread i owns hidden index i.
// W2 (64x64) in padded shared memory; all other params in registers.
__global__ __launch_bounds__(64) void ttt_kernel(
    const float* __restrict__ ts, const float* __restrict__ xs,
    const int*   __restrict__ mask,
    const float* __restrict__ W1g, const float* __restrict__ b1g,
    const float* __restrict__ W2g, const float* __restrict__ b2g,
    const float* __restrict__ W3g, const float* __restrict__ b3g,
    float* __restrict__ out, int T)
{
    __shared__ __align__(16) float W2s[HDIM * WSTRIDE];
    __shared__ __align__(16) float h1s[HDIM];
    __shared__ __align__(16) float dz2s[HDIM];
    __shared__ float red[2];

    const int b    = blockIdx.x;
    const int i    = threadIdx.x;       // 0..63
    const int lane = i & 31;
    const int warp = i >> 5;

    // Load theta0. W2 row i -> smem row i (16B-aligned: i*WSTRIDE*4 = i*272).
    #pragma unroll
    for (int kk = 0; kk < 16; kk++) {
        float4 v = *(const float4*)(W2g + i * HDIM + 4 * kk);
        *(float4*)(W2s + i * WSTRIDE + 4 * kk) = v;
    }
    float w1a = W1g[2 * i];
    float w1b = W1g[2 * i + 1];
    float b1i = b1g[i];
    float b2i = b2g[i];
    float w3i = W3g[i];
    float b3  = b3g[0];

    const float* xrow = xs + (size_t)b * T;
    const int*   mrow = mask + (size_t)b * (T - 1);

    float x0 = xrow[0];
    float x_hat = x0, x_prev = x0, t_prev = ts[0];
    if (i == 0) out[(size_t)b * T] = x0;
    __syncthreads();

    for (int s = 1; s < T; s++) {
        const float t_c    = ts[s];
        const float x_true = xrow[s];
        // mask: nonzero 4-byte word == true (covers int32 0/1 and float 0.0/1.0)
        const float x_t    = (mrow[s - 1] != 0) ? x_true : x_hat;

        #pragma unroll 1
        for (int g = 0; g < NUM_GRAD_STEPS; g++) {
            // ---- forward at (t_c, x_prev) ----
            float h1 = tanhf(fmaf(w1a, t_c, fmaf(w1b, x_prev, b1i)));
            h1s[i] = h1;
            __syncthreads();

            float a0 = 0.f, a1 = 0.f, a2 = 0.f, a3 = 0.f;
            const float* wr = W2s + i * WSTRIDE;
            #pragma unroll
            for (int kk = 0; kk < 16; kk++) {
                float4 hv = *(const float4*)(h1s + 4 * kk);   // broadcast
                float4 wv = *(const float4*)(wr + 4 * kk);    // row, conflict-free
                a0 = fmaf(wv.x, hv.x, a0);
                a1 = fmaf(wv.y, hv.y, a1);
                a2 = fmaf(wv.z, hv.z, a2);
                a3 = fmaf(wv.w, hv.w, a3);
            }
            float z2 = b2i + ((a0 + a1) + (a2 + a3));
            float h2 = tanhf(z2);

            // pred = W3 . h2 + b3 : 2-warp reduction
            float pp = w3i * h2;
            #pragma unroll
            for (int off = 16; off; off >>= 1)
                pp += __shfl_xor_sync(0xffffffffu, pp, off);
            if (lane == 0) red[warp] = pp;
            __syncthreads();
            const float pred  = (red[0] + red[1]) + b3;
            const float dpred = 2.0f * (pred - x_t);

            // ---- backward (all grads at OLD theta) ----
            const float dz2 = dpred * w3i * (1.0f - h2 * h2);   // uses old W3
            dz2s[i] = dz2;
            // W3/b3/b2 updates (grads already extracted)
            w3i = fmaf(-INNER_LR * dpred, h2, w3i);
            b3  = fmaf(-INNER_LR, dpred, b3);
            b2i = fmaf(-INNER_LR, dz2, b2i);
            __syncthreads();

            // column pass: d_h1[i] = sum_j W2_old[j][i]*dz2[j], fused with
            // W2[j][i] -= lr*dz2[j]*h1[i]. Disjoint columns per thread.
            float d0 = 0.f, d1 = 0.f, d2 = 0.f, d3 = 0.f;
            const float am = -(INNER_LR * h1);   // h1 == h1s[i]
            #pragma unroll
            for (int jj = 0; jj < 16; jj++) {
                float4 dv = *(const float4*)(dz2s + 4 * jj);   // broadcast
                float* p = W2s + (4 * jj) * WSTRIDE + i;
                float w0 = p[0];
                float w1_ = p[WSTRIDE];
                float w2_ = p[2 * WSTRIDE];
                float w3_ = p[3 * WSTRIDE];
                d0 = fmaf(w0,  dv.x, d0);
                d1 = fmaf(w1_, dv.y, d1);
                d2 = fmaf(w2_, dv.z, d2);
                d3 = fmaf(w3_, dv.w, d3);
                p[0]           = fmaf(am, dv.x, w0);
                p[WSTRIDE]     = fmaf(am, dv.y, w1_);
                p[2 * WSTRIDE] = fmaf(am, dv.z, w2_);
                p[3 * WSTRIDE] = fmaf(am, dv.w, w3_);
            }
            const float dh1 = (d0 + d1) + (d2 + d3);
            const float dz1 = dh1 * (1.0f - h1 * h1);
            w1a = fmaf(-INNER_LR * dz1, t_c,    w1a);
            w1b = fmaf(-INNER_LR * dz1, x_prev, w1b);
            b1i = fmaf(-INNER_LR, dz1, b1i);
            // no barrier needed: next iteration's post-h1s barrier orders W2s
        }

        // ---- final forward with updated theta at (t_c + dt, x_true) ----
        const float dt  = t_c - t_prev;
        const float tin = t_c + dt;
        float h1 = tanhf(fmaf(w1a, tin, fmaf(w1b, x_true, b1i)));
        h1s[i] = h1;
        __syncthreads();   // orders last column-pass W2s writes before row reads

        float a0 = 0.f, a1 = 0.f, a2 = 0.f, a3 = 0.f;
        const float* wr = W2s + i * WSTRIDE;
        #pragma unroll
        for (int kk = 0; kk < 16; kk++) {
            float4 hv = *(const float4*)(h1s + 4 * kk);
            float4 wv = *(const float4*)(wr + 4 * kk);
            a0 = fmaf(wv.x, hv.x, a0);
            a1 = fmaf(wv.y, hv.y, a1);
            a2 = fmaf(wv.z, hv.z, a2);
            a3 = fmaf(wv.w, hv.w, a3);
        }
        float z2 = b2i + ((a0 + a1) + (a2 + a3));
        float h2 = tanhf(z2);
        float pp = w3i * h2;
        #pragma unroll
        for (int off = 16; off; off >>= 1)
            pp += __shfl_xor_sync(0xffffffffu, pp, off);
        if (lane == 0) red[warp] = pp;
        __syncthreads();
        x_hat = (red[0] + red[1]) + b3;

        if (i == 0) out[(size_t)b * T + s] = x_hat;
        x_prev = x_true;
        t_prev = t_c;
    }
}

extern "C" void kernel_launch(void* const* d_in, const int* in_sizes, int n_in,
                              void* d_out, int out_size) {
    const float* ts   = (const float*)d_in[0];
    const float* xs   = (const float*)d_in[1];
    const int*   mask = (const int*)  d_in[2];
    const float* W1   = (const float*)d_in[3];
    const float* b1   = (const float*)d_in[4];
    const float* W2   = (const float*)d_in[5];
    const float* b2   = (const float*)d_in[6];
    const float* W3   = (const float*)d_in[7];
    const float* b3   = (const float*)d_in[8];

    const int T = in_sizes[0];
    const int B = in_sizes[1] / T;

    ttt_kernel<<<B, HDIM>>>(ts, xs, mask, W1, b1, W2, b2, W3, b3,
                            (float*)d_out, T);
}

// round 2
// speedup vs baseline: 1.0004x; 1.0004x over previous
#include <cuda_runtime.h>

#define HDIM 64
#define WSTRIDE 68          // 64 + 4 pad: conflict-free rows (LDS.128) AND columns (scalar)
#define NUM_GRAD_STEPS 4
#define INNER_LR 0.01f

// One block (64 threads) per batch element. Thread i owns hidden index i.
// W2 (64x64) in padded shared memory; all other params in registers.
__global__ __launch_bounds__(64) void ttt_kernel(
    const float* __restrict__ ts, const float* __restrict__ xs,
    const int*   __restrict__ mask,
    const float* __restrict__ W1g, const float* __restrict__ b1g,
    const float* __restrict__ W2g, const float* __restrict__ b2g,
    const float* __restrict__ W3g, const float* __restrict__ b3g,
    float* __restrict__ out, int T)
{
    __shared__ __align__(16) float W2s[HDIM * WSTRIDE];
    __shared__ __align__(16) float h1s[HDIM];
    __shared__ __align__(16) float dz2s[HDIM];
    __shared__ float red[2];

    const int b    = blockIdx.x;
    const int i    = threadIdx.x;       // 0..63
    const int lane = i & 31;
    const int warp = i >> 5;

    // Load theta0. W2 row i -> smem row i (16B-aligned: i*WSTRIDE*4 = i*272).
    #pragma unroll
    for (int kk = 0; kk < 16; kk++) {
        float4 v = *(const float4*)(W2g + i * HDIM + 4 * kk);
        *(float4*)(W2s + i * WSTRIDE + 4 * kk) = v;
    }
    float w1a = W1g[2 * i];
    float w1b = W1g[2 * i + 1];
    float b1i = b1g[i];
    float b2i = b2g[i];
    float w3i = W3g[i];
    float b3  = b3g[0];

    const float* xrow = xs + (size_t)b * T;
    const int*   mrow = mask + (size_t)b * (T - 1);

    float x0 = xrow[0];
    float x_hat = x0, x_prev = x0, t_prev = ts[0];
    if (i == 0) out[(size_t)b * T] = x0;
    __syncthreads();

    for (int s = 1; s < T; s++) {
        const float t_c    = ts[s];
        const float x_true = xrow[s];
        // mask: nonzero 4-byte word == true (covers int32 0/1 and float 0.0/1.0)
        const float x_t    = (mrow[s - 1] != 0) ? x_true : x_hat;

        #pragma unroll 1
        for (int g = 0; g < NUM_GRAD_STEPS; g++) {
            // ---- forward at (t_c, x_prev) ----
            float h1 = tanhf(fmaf(w1a, t_c, fmaf(w1b, x_prev, b1i)));
            h1s[i] = h1;
            __syncthreads();

            float a0 = 0.f, a1 = 0.f, a2 = 0.f, a3 = 0.f;
            const float* wr = W2s + i * WSTRIDE;
            #pragma unroll
            for (int kk = 0; kk < 16; kk++) {
                float4 hv = *(const float4*)(h1s + 4 * kk);   // broadcast
                float4 wv = *(const float4*)(wr + 4 * kk);    // row, conflict-free
                a0 = fmaf(wv.x, hv.x, a0);
                a1 = fmaf(wv.y, hv.y, a1);
                a2 = fmaf(wv.z, hv.z, a2);
                a3 = fmaf(wv.w, hv.w, a3);
            }
            float z2 = b2i + ((a0 + a1) + (a2 + a3));
            float h2 = tanhf(z2);

            // pred = W3 . h2 + b3 : 2-warp reduction
            float pp = w3i * h2;
            #pragma unroll
            for (int off = 16; off; off >>= 1)
                pp += __shfl_xor_sync(0xffffffffu, pp, off);
            if (lane == 0) red[warp] = pp;
            __syncthreads();
            const float pred  = (red[0] + red[1]) + b3;
            const float dpred = 2.0f * (pred - x_t);

            // ---- backward (all grads at OLD theta) ----
            const float dz2 = dpred * w3i * (1.0f - h2 * h2);   // uses old W3
            dz2s[i] = dz2;
            // W3/b3/b2 updates (grads already extracted)
            w3i = fmaf(-INNER_LR * dpred, h2, w3i);
            b3  = fmaf(-INNER_LR, dpred, b3);
            b2i = fmaf(-INNER_LR, dz2, b2i);
            __syncthreads();

            // column pass: d_h1[i] = sum_j W2_old[j][i]*dz2[j], fused with
            // W2[j][i] -= lr*dz2[j]*h1[i]. Disjoint columns per thread.
            float d0 = 0.f, d1 = 0.f, d2 = 0.f, d3 = 0.f;
            const float am = -(INNER_LR * h1);   // h1 == h1s[i]
            #pragma unroll
            for (int jj = 0; jj < 16; jj++) {
                float4 dv = *(const float4*)(dz2s + 4 * jj);   // broadcast
                float* p = W2s + (4 * jj) * WSTRIDE + i;
                float w0 = p[0];
                float w1_ = p[WSTRIDE];
                float w2_ = p[2 * WSTRIDE];
                float w3_ = p[3 * WSTRIDE];
                d0 = fmaf(w0,  dv.x, d0);
                d1 = fmaf(w1_, dv.y, d1);
                d2 = fmaf(w2_, dv.z, d2);
                d3 = fmaf(w3_, dv.w, d3);
                p[0]           = fmaf(am, dv.x, w0);
                p[WSTRIDE]     = fmaf(am, dv.y, w1_);
                p[2 * WSTRIDE] = fmaf(am, dv.z, w2_);
                p[3 * WSTRIDE] = fmaf(am, dv.w, w3_);
            }
            const float dh1 = (d0 + d1) + (d2 + d3);
            const float dz1 = dh1 * (1.0f - h1 * h1);
            w1a = fmaf(-INNER_LR * dz1, t_c,    w1a);
            w1b = fmaf(-INNER_LR * dz1, x_prev, w1b);
            b1i = fmaf(-INNER_LR, dz1, b1i);
            // no barrier needed: next iteration's post-h1s barrier orders W2s
        }

        // ---- final forward with updated theta at (t_c + dt, x_true) ----
        const float dt  = t_c - t_prev;
        const float tin = t_c + dt;
        float h1 = tanhf(fmaf(w1a, tin, fmaf(w1b, x_true, b1i)));
        h1s[i] = h1;
        __syncthreads();   // orders last column-pass W2s writes before row reads

        float a0 = 0.f, a1 = 0.f, a2 = 0.f, a3 = 0.f;
        const float* wr = W2s + i * WSTRIDE;
        #pragma unroll
        for (int kk = 0; kk < 16; kk++) {
            float4 hv = *(const float4*)(h1s + 4 * kk);
            float4 wv = *(const float4*)(wr + 4 * kk);
            a0 = fmaf(wv.x, hv.x, a0);
            a1 = fmaf(wv.y, hv.y, a1);
            a2 = fmaf(wv.z, hv.z, a2);
            a3 = fmaf(wv.w, hv.w, a3);
        }
        float z2 = b2i + ((a0 + a1) + (a2 + a3));
        float h2 = tanhf(z2);
        float pp = w3i * h2;
        #pragma unroll
        for (int off = 16; off; off >>= 1)
            pp += __shfl_xor_sync(0xffffffffu, pp, off);
        if (lane == 0) red[warp] = pp;
        __syncthreads();
        x_hat = (red[0] + red[1]) + b3;

        if (i == 0) out[(size_t)b * T + s] = x_hat;
        x_prev = x_true;
        t_prev = t_c;
    }
}

extern "C" void kernel_launch(void* const* d_in, const int* in_sizes, int n_in,
                              void* d_out, int out_size) {
    const float* ts   = (const float*)d_in[0];
    const float* xs   = (const float*)d_in[1];
    const int*   mask = (const int*)  d_in[2];
    const float* W1   = (const float*)d_in[3];
    const float* b1   = (const float*)d_in[4];
    const float* W2   = (const float*)d_in[5];
    const float* b2   = (const float*)d_in[6];
    const float* W3   = (const float*)d_in[7];
    const float* b3   = (const float*)d_in[8];

    const int T = in_sizes[0];
    const int B = in_sizes[1] / T;

    ttt_kernel<<<B, HDIM>>>(ts, xs, mask, W1, b1, W2, b2, W3, b3,
                            (float*)d_out, T);
}

// round 3
// speedup vs baseline: 1.2217x; 1.2212x over previous
#include <cuda_runtime.h>

#define HDIM 64
#define NUM_GRAD_STEPS 4
#define INNER_LR 0.01f

typedef unsigned long long u64;

// ---- packed fp32x2 helpers (ptxas won't auto-fuse; PTX fma.rn.f32x2) ----
__device__ __forceinline__ u64 pack2(float lo, float hi) {
    u64 r; asm("mov.b64 %0, {%1,%2};" : "=l"(r) : "f"(lo), "f"(hi)); return r;
}
__device__ __forceinline__ float2 unpack2(u64 v) {
    float2 f; asm("mov.b64 {%0,%1}, %2;" : "=f"(f.x), "=f"(f.y) : "l"(v)); return f;
}
__device__ __forceinline__ u64 fma2(u64 a, u64 b, u64 c) {
    u64 d; asm("fma.rn.f32x2 %0, %1, %2, %3;" : "=l"(d) : "l"(a), "l"(b), "l"(c)); return d;
}

// One block (64 threads) per batch element. Thread i owns hidden index i.
// W2 lives ONLY in registers: w2row[32] = row i (pairs), w2col[32] = column i
// (pairs). Shared memory carries just the h1 / dz2 broadcast vectors.
__global__ __launch_bounds__(64) void ttt_kernel(
    const float* __restrict__ ts, const float* __restrict__ xs,
    const int*   __restrict__ mask,
    const float* __restrict__ W1g, const float* __restrict__ b1g,
    const float* __restrict__ W2g, const float* __restrict__ b2g,
    const float* __restrict__ W3g, const float* __restrict__ b3g,
    float* __restrict__ out, int T)
{
    __shared__ __align__(16) float h1s[HDIM];
    __shared__ __align__(16) float dz2s[HDIM];
    __shared__ float red[2];

    const int b    = blockIdx.x;
    const int i    = threadIdx.x;       // 0..63
    const int lane = i & 31;
    const int warp = i >> 5;

    // ---- load theta0 ----
    u64 w2row[32];   // w2row[m] = (W2[i][2m], W2[i][2m+1])
    u64 w2col[32];   // w2col[m] = (W2[2m][i], W2[2m+1][i])
    #pragma unroll
    for (int k = 0; k < 16; k++) {
        float4 v = *(const float4*)(W2g + i * HDIM + 4 * k);
        w2row[2 * k]     = pack2(v.x, v.y);
        w2row[2 * k + 1] = pack2(v.z, v.w);
    }
    #pragma unroll
    for (int m = 0; m < 32; m++) {
        float lo = W2g[(2 * m) * HDIM + i];       // coalesced across threads
        float hi = W2g[(2 * m + 1) * HDIM + i];
        w2col[m] = pack2(lo, hi);
    }
    float w1a = W1g[2 * i];
    float w1b = W1g[2 * i + 1];
    float b1i = b1g[i];
    float b2i = b2g[i];
    float w3i = W3g[i];
    float b3  = b3g[0];

    const float* xrow = xs + (size_t)b * T;
    const int*   mrow = mask + (size_t)b * (T - 1);

    const float x0 = xrow[0];
    float x_hat = x0, x_prev = x0, t_prev = ts[0];
    if (i == 0) out[(size_t)b * T] = x0;
    __syncthreads();

    // prefetched per-step scalars
    float t_c = ts[1], x_true = xrow[1];
    int   mcur = mrow[0];

    for (int s = 1; s < T; s++) {
        // prefetch next step (hide L2 latency behind this step's compute)
        float t_n = 0.f, x_n = 0.f; int m_n = 0;
        if (s + 1 < T) { t_n = ts[s + 1]; x_n = xrow[s + 1]; m_n = mrow[s]; }

        const float x_t = (mcur != 0) ? x_true : x_hat;

        float h1;
        #pragma unroll 1
        for (int g = 0; g < NUM_GRAD_STEPS; g++) {
            // ---- forward at (t_c, x_prev) ----
            h1 = tanhf(fmaf(w1a, t_c, fmaf(w1b, x_prev, b1i)));
            h1s[i] = h1;
            __syncthreads();                                  // sync A

            u64 a0 = pack2(b2i, 0.f), a1 = 0ull, a2 = 0ull, a3 = 0ull;
            #pragma unroll
            for (int k = 0; k < 8; k++) {
                float4 h0 = *(const float4*)(h1s + 8 * k);      // broadcast
                float4 h4 = *(const float4*)(h1s + 8 * k + 4);
                a0 = fma2(w2row[4 * k],     pack2(h0.x, h0.y), a0);
                a1 = fma2(w2row[4 * k + 1], pack2(h0.z, h0.w), a1);
                a2 = fma2(w2row[4 * k + 2], pack2(h4.x, h4.y), a2);
                a3 = fma2(w2row[4 * k + 3], pack2(h4.z, h4.w), a3);
            }
            float2 s0 = unpack2(a0), s1 = unpack2(a1), s2 = unpack2(a2), s3 = unpack2(a3);
            const float z2 = ((s0.x + s0.y) + (s1.x + s1.y)) +
                             ((s2.x + s2.y) + (s3.x + s3.y));
            const float h2 = tanhf(z2);

            // pred = W3 . h2 + b3 : 2-warp reduction
            float pp = w3i * h2;
            #pragma unroll
            for (int off = 16; off; off >>= 1)
                pp += __shfl_xor_sync(0xffffffffu, pp, off);
            if (lane == 0) red[warp] = pp;
            __syncthreads();                                  // sync B
            const float pred  = (red[0] + red[1]) + b3;
            const float dpred = 2.0f * (pred - x_t);

            // ---- backward (all grads at OLD theta) ----
            const float dz2 = dpred * w3i * (1.0f - h2 * h2);  // old W3
            dz2s[i] = dz2;
            w3i = fmaf(-INNER_LR * dpred, h2, w3i);
            b3  = fmaf(-INNER_LR, dpred, b3);
            b2i = fmaf(-INNER_LR, dz2, b2i);

            // row update: W2[i][k] -= lr*dz2_i*h1[k]  (h1s valid since sync A)
            const u64 amrow = pack2(-INNER_LR * dz2, -INNER_LR * dz2);
            #pragma unroll
            for (int k = 0; k < 8; k++) {
                float4 h0 = *(const float4*)(h1s + 8 * k);
                float4 h4 = *(const float4*)(h1s + 8 * k + 4);
                w2row[4 * k]     = fma2(amrow, pack2(h0.x, h0.y), w2row[4 * k]);
                w2row[4 * k + 1] = fma2(amrow, pack2(h0.z, h0.w), w2row[4 * k + 1]);
                w2row[4 * k + 2] = fma2(amrow, pack2(h4.x, h4.y), w2row[4 * k + 2]);
                w2row[4 * k + 3] = fma2(amrow, pack2(h4.z, h4.w), w2row[4 * k + 3]);
            }
            __syncthreads();                                  // sync C

            // fused column pass on register copy:
            //   dh1 += W2_old[j][i]*dz2[j];  W2[j][i] -= lr*dz2[j]*h1_i
            const u64 amcol = pack2(-INNER_LR * h1, -INNER_LR * h1);
            u64 d0 = 0ull, d1 = 0ull, d2 = 0ull, d3 = 0ull;
            #pragma unroll
            for (int j = 0; j < 8; j++) {
                float4 v0 = *(const float4*)(dz2s + 8 * j);     // broadcast
                float4 v4 = *(const float4*)(dz2s + 8 * j + 4);
                u64 p0 = pack2(v0.x, v0.y), p1 = pack2(v0.z, v0.w);
                u64 p2 = pack2(v4.x, v4.y), p3 = pack2(v4.z, v4.w);
                d0 = fma2(w2col[4 * j],     p0, d0);
                d1 = fma2(w2col[4 * j + 1], p1, d1);
                d2 = fma2(w2col[4 * j + 2], p2, d2);
                d3 = fma2(w2col[4 * j + 3], p3, d3);
                w2col[4 * j]     = fma2(amcol, p0, w2col[4 * j]);
                w2col[4 * j + 1] = fma2(amcol, p1, w2col[4 * j + 1]);
                w2col[4 * j + 2] = fma2(amcol, p2, w2col[4 * j + 2]);
                w2col[4 * j + 3] = fma2(amcol, p3, w2col[4 * j + 3]);
            }
            float2 e0 = unpack2(d0), e1 = unpack2(d1), e2 = unpack2(d2), e3 = unpack2(d3);
            const float dh1 = ((e0.x + e0.y) + (e1.x + e1.y)) +
                              ((e2.x + e2.y) + (e3.x + e3.y));
            const float dz1 = dh1 * (1.0f - h1 * h1);
            w1a = fmaf(-INNER_LR * dz1, t_c,    w1a);
            w1b = fmaf(-INNER_LR * dz1, x_prev, w1b);
            b1i = fmaf(-INNER_LR, dz1, b1i);
        }

        // ---- final forward with updated theta at (t_c + dt, x_true) ----
        const float tin = t_c + (t_c - t_prev);
        float hf = tanhf(fmaf(w1a, tin, fmaf(w1b, x_true, b1i)));
        h1s[i] = hf;                      // writes after sync C: no race
        __syncthreads();

        u64 a0 = pack2(b2i, 0.f), a1 = 0ull, a2 = 0ull, a3 = 0ull;
        #pragma unroll
        for (int k = 0; k < 8; k++) {
            float4 h0 = *(const float4*)(h1s + 8 * k);
            float4 h4 = *(const float4*)(h1s + 8 * k + 4);
            a0 = fma2(w2row[4 * k],     pack2(h0.x, h0.y), a0);
            a1 = fma2(w2row[4 * k + 1], pack2(h0.z, h0.w), a1);
            a2 = fma2(w2row[4 * k + 2], pack2(h4.x, h4.y), a2);
            a3 = fma2(w2row[4 * k + 3], pack2(h4.z, h4.w), a3);
        }
        float2 s0 = unpack2(a0), s1 = unpack2(a1), s2 = unpack2(a2), s3 = unpack2(a3);
        const float z2 = ((s0.x + s0.y) + (s1.x + s1.y)) +
                         ((s2.x + s2.y) + (s3.x + s3.y));
        const float h2 = tanhf(z2);
        float pp = w3i * h2;
        #pragma unroll
        for (int off = 16; off; off >>= 1)
            pp += __shfl_xor_sync(0xffffffffu, pp, off);
        if (lane == 0) red[warp] = pp;
        __syncthreads();
        x_hat = (red[0] + red[1]) + b3;

        if (i == 0) out[(size_t)b * T + s] = x_hat;
        x_prev = x_true;
        t_prev = t_c;
        t_c = t_n; x_true = x_n; mcur = m_n;
    }
}

extern "C" void kernel_launch(void* const* d_in, const int* in_sizes, int n_in,
                              void* d_out, int out_size) {
    const float* ts   = (const float*)d_in[0];
    const float* xs   = (const float*)d_in[1];
    const int*   mask = (const int*)  d_in[2];
    const float* W1   = (const float*)d_in[3];
    const float* b1   = (const float*)d_in[4];
    const float* W2   = (const float*)d_in[5];
    const float* b2   = (const float*)d_in[6];
    const float* W3   = (const float*)d_in[7];
    const float* b3   = (const float*)d_in[8];

    const int T = in_sizes[0];
    const int B = in_sizes[1] / T;

    ttt_kernel<<<B, HDIM>>>(ts, xs, mask, W1, b1, W2, b2, W3, b3,
                            (float*)d_out, T);
}